// round 2
// baseline (speedup 1.0000x reference)
#include <cuda_runtime.h>
#include <math.h>

#define BATCH 4
#define CH    128
#define HH    384
#define WW    384
#define HW    (HH*WW)          // 147456
#define NPIX  (BATCH*HW)       // 589824

// Scratch (allocation-free: __device__ globals)
__device__ float         g_T[(size_t)NPIX * CH];   // [B,H,W,C] transposed features (302 MB)
__device__ float         g_nf2[NPIX];              // per-pixel sum of squares
__device__ unsigned char g_sel[NPIX];              // selected boundary (interior) mask
__device__ float         g_acc[BATCH];             // per-batch sum of (cos-lab)^2
__device__ int           g_cnt[BATCH];             // per-batch selected-pixel count
__device__ int           g_bnd[BATCH];             // per-batch "any boundary pixel" flag

// ---------------------------------------------------------------------------
// 0. zero accumulators + nf2
__global__ void zero_kernel() {
    int stride = gridDim.x * blockDim.x;
    for (int i = blockIdx.x * blockDim.x + threadIdx.x; i < NPIX; i += stride)
        g_nf2[i] = 0.0f;
    if (blockIdx.x == 0 && threadIdx.x < BATCH) {
        g_acc[threadIdx.x] = 0.0f;
        g_cnt[threadIdx.x] = 0;
        g_bnd[threadIdx.x] = 0;
    }
}

// ---------------------------------------------------------------------------
// 1. transpose [B,C,H,W] -> [B,H,W,C], fused partial norm reduction
//    block: 32x8 threads, tile: 32 pixels x 32 channels
__global__ void transpose_kernel(const float* __restrict__ er) {
    __shared__ float tile[32][33];
    __shared__ float red[8][32];
    int tx = threadIdx.x, ty = threadIdx.y;
    int p0 = blockIdx.x * 32;        // pixel base (linear over H*W)
    int c0 = blockIdx.y * 32;        // channel base
    int b  = blockIdx.z;

    float sq = 0.0f;
#pragma unroll
    for (int i = 0; i < 4; i++) {
        int c = c0 + ty + 8 * i;
        float v = er[((size_t)(b * CH + c)) * HW + p0 + tx];   // coalesced over tx
        tile[ty + 8 * i][tx] = v;
        sq += v * v;
    }
    red[ty][tx] = sq;
    __syncthreads();
    if (ty == 0) {
        float s = 0.0f;
#pragma unroll
        for (int j = 0; j < 8; j++) s += red[j][tx];
        atomicAdd(&g_nf2[b * HW + p0 + tx], s);
    }
#pragma unroll
    for (int i = 0; i < 4; i++) {
        int p = p0 + ty + 8 * i;
        g_T[((size_t)(b * HW + p)) * CH + c0 + tx] = tile[tx][ty + 8 * i]; // coalesced over tx
    }
}

// ---------------------------------------------------------------------------
// 2. boundary / selection mask, per-batch counts + validity
__global__ void mask_kernel(const int* __restrict__ seg, const int* __restrict__ gtb) {
    int p = blockIdx.x * blockDim.x + threadIdx.x;   // grid sized exactly NPIX
    int b = p / HW;
    int rem = p - b * HW;
    int y = rem / WW;
    int x = rem - y * WW;

    int gt = gtb[p];                    if (gt == 255) gt = 0;
    int s1 = seg[((size_t)(b * 2 + 1)) * HW + rem]; if (s1 == 255) s1 = 0;
    bool bnd = (gt * s1) > 0;
    bool inter = (y >= 2) && (y <= HH - 3) && (x >= 2) && (x <= WW - 3);
    bool s = bnd && inter;
    g_sel[p] = s ? 1 : 0;

    unsigned selm = __ballot_sync(0xffffffffu, s);
    unsigned bndm = __ballot_sync(0xffffffffu, bnd);
    if ((threadIdx.x & 31) == 0) {
        if (selm) atomicAdd(&g_cnt[b], __popc(selm));
        if (bndm) atomicOr(&g_bnd[b], 1);
    }
}

// ---------------------------------------------------------------------------
// 3. main: one warp per pixel; 24 neighbor dots from pixel-major features
__launch_bounds__(256)
__global__ void ctx_kernel(const int* __restrict__ seg) {
    __shared__ float blockAcc;
    if (threadIdx.x == 0) blockAcc = 0.0f;
    __syncthreads();

    int p    = blockIdx.x * 8 + (threadIdx.x >> 5);   // 8 warps/block, 1 pixel/warp
    int lane = threadIdx.x & 31;

    if (g_sel[p]) {
        int b   = p / HW;
        int rem = p - b * HW;

        float4 c4 = ((const float4*)(g_T + (size_t)p * CH))[lane];
        float dc = fmaxf(sqrtf(g_nf2[p]), 1e-8f);
        int s0 = seg[((size_t)(b * 2)) * HW + rem];
        int s1 = seg[((size_t)(b * 2 + 1)) * HW + rem];

        float acc = 0.0f;
#pragma unroll
        for (int ki = 0; ki < 5; ki++) {
#pragma unroll
            for (int kj = 0; kj < 5; kj++) {
                if (ki == 2 && kj == 2) continue;
                int off  = (ki - 2) * WW + (kj - 2);
                int q    = p + off;       // interior => same batch, in-bounds
                int remq = rem + off;

                float4 n4 = ((const float4*)(g_T + (size_t)q * CH))[lane];
                float d = c4.x * n4.x + c4.y * n4.y + c4.z * n4.z + c4.w * n4.w;
#pragma unroll
                for (int sh = 16; sh > 0; sh >>= 1)
                    d += __shfl_xor_sync(0xffffffffu, d, sh);

                float dn  = fmaxf(sqrtf(g_nf2[q]), 1e-8f);
                float cosv = d / (dc * dn);
                int t0 = seg[((size_t)(b * 2)) * HW + remq];
                int t1 = seg[((size_t)(b * 2 + 1)) * HW + remq];
                float lab = (float)(s0 * t0 + s1 * t1);
                float e = cosv - lab;
                acc += e * e;
            }
        }
        if (lane == 0) atomicAdd(&blockAcc, acc);
    }
    __syncthreads();
    if (threadIdx.x == 0 && blockAcc != 0.0f) {
        int b = (blockIdx.x * 8) / HW;   // block's 8 pixels share one batch (HW % 8 == 0)
        atomicAdd(&g_acc[b], blockAcc);
    }
}

// ---------------------------------------------------------------------------
// 4. finalize: per-batch normalization, valid-batch average, NaN guard
__global__ void fin_kernel(float* __restrict__ out) {
    if (threadIdx.x == 0) {
        float tot = 0.0f, nv = 0.0f;
        for (int b = 0; b < BATCH; b++) {
            float lb = g_acc[b] / fmaxf((float)g_cnt[b], 1.0f) / 24.0f;
            if (g_bnd[b]) { tot += lb; nv += 1.0f; }
        }
        tot = tot / fmaxf(nv, 1.0f);
        if (isnan(tot)) tot = 0.0f;
        out[0] = tot;
    }
}

// ---------------------------------------------------------------------------
extern "C" void kernel_launch(void* const* d_in, const int* in_sizes, int n_in,
                              void* d_out, int out_size) {
    const float* er  = (const float*)d_in[0];   // er_input [4,128,384,384] f32
    const int*   seg = (const int*)d_in[1];     // seg_label [4,2,384,384] i32
    const int*   gtb = (const int*)d_in[2];     // gt_boundary_seg [4,384,384] i32
    float*       out = (float*)d_out;

    zero_kernel<<<256, 256>>>();
    transpose_kernel<<<dim3(HW / 32, CH / 32, BATCH), dim3(32, 8)>>>(er);
    mask_kernel<<<NPIX / 256, 256>>>(seg, gtb);
    ctx_kernel<<<NPIX / 8, 256>>>(seg);
    fin_kernel<<<1, 32>>>(out);
}

// round 3
// speedup vs baseline: 2.2087x; 2.2087x over previous
#include <cuda_runtime.h>
#include <math.h>

#define BATCH 4
#define CH    128
#define HH    384
#define WW    384
#define HW    (HH*WW)          // 147456
#define NPIX  (BATCH*HW)       // 589824

// max selectable pixels (interior only)
#define MAXSEL ((HH-4)*(WW-4)*BATCH)      // 577600
#define CTX_BLOCKS (((MAXSEL + 3) / 4 + 7) / 8)

// Scratch (allocation-free: __device__ globals)
__device__ float         g_T[(size_t)NPIX * CH];   // [B,H,W,C] transposed features
__device__ float         g_nf2[NPIX];              // per-pixel sum of squares
__device__ float         g_inv[NPIX];              // 1 / max(||f||, 1e-8)
__device__ unsigned char g_cls[NPIX];              // class (seg_label channel 1)
__device__ int           g_list[NPIX];             // compacted selected pixel ids
__device__ int           g_nsel;                   // number selected (total)
__device__ float         g_acc[BATCH];
__device__ int           g_cnt[BATCH];
__device__ int           g_bnd[BATCH];

__constant__ int c_off[24] = {
    -770,-769,-768,-767,-766,
    -386,-385,-384,-383,-382,
      -2,  -1,   1,   2,
     382, 383, 384, 385, 386,
     766, 767, 768, 769, 770 };

// ---------------------------------------------------------------------------
// 0. zero accumulators + nf2
__global__ void zero_kernel() {
    int stride = gridDim.x * blockDim.x;
    for (int i = blockIdx.x * blockDim.x + threadIdx.x; i < NPIX; i += stride)
        g_nf2[i] = 0.0f;
    if (blockIdx.x == 0 && threadIdx.x == 0) g_nsel = 0;
    if (blockIdx.x == 0 && threadIdx.x < BATCH) {
        g_acc[threadIdx.x] = 0.0f;
        g_cnt[threadIdx.x] = 0;
        g_bnd[threadIdx.x] = 0;
    }
}

// ---------------------------------------------------------------------------
// 1. transpose [B,C,H,W] -> [B,H,W,C], fused partial norm reduction
__global__ void transpose_kernel(const float* __restrict__ er) {
    __shared__ float tile[32][33];
    __shared__ float red[8][32];
    int tx = threadIdx.x, ty = threadIdx.y;
    int p0 = blockIdx.x * 32;
    int c0 = blockIdx.y * 32;
    int b  = blockIdx.z;

    float sq = 0.0f;
#pragma unroll
    for (int i = 0; i < 4; i++) {
        int c = c0 + ty + 8 * i;
        float v = er[((size_t)(b * CH + c)) * HW + p0 + tx];
        tile[ty + 8 * i][tx] = v;
        sq += v * v;
    }
    red[ty][tx] = sq;
    __syncthreads();
    if (ty == 0) {
        float s = 0.0f;
#pragma unroll
        for (int j = 0; j < 8; j++) s += red[j][tx];
        atomicAdd(&g_nf2[b * HW + p0 + tx], s);
    }
#pragma unroll
    for (int i = 0; i < 4; i++) {
        int p = p0 + ty + 8 * i;
        g_T[((size_t)(b * HW + p)) * CH + c0 + tx] = tile[tx][ty + 8 * i];
    }
}

// ---------------------------------------------------------------------------
// 2. prep: selection mask + compaction, inv-norm, class byte, counts
__global__ void prep_kernel(const int* __restrict__ seg, const int* __restrict__ gtb) {
    int p = blockIdx.x * blockDim.x + threadIdx.x;   // grid == NPIX exactly
    int b = p / HW;
    int rem = p - b * HW;
    int y = rem / WW;
    int x = rem - y * WW;
    int lane = threadIdx.x & 31;

    int s1r = seg[((size_t)(b * 2 + 1)) * HW + rem];
    int gt = gtb[p];                 if (gt == 255) gt = 0;
    int s1 = s1r;                    if (s1 == 255) s1 = 0;
    bool bnd = (gt * s1) > 0;
    bool inter = (y >= 2) && (y <= HH - 3) && (x >= 2) && (x <= WW - 3);
    bool s = bnd && inter;

    g_cls[p] = (unsigned char)s1r;
    float nfv = sqrtf(g_nf2[p]);
    g_inv[p] = 1.0f / fmaxf(nfv, 1e-8f);

    unsigned selm = __ballot_sync(0xffffffffu, s);
    unsigned bndm = __ballot_sync(0xffffffffu, bnd);
    int base = 0;
    if (lane == 0 && selm) {
        base = atomicAdd(&g_nsel, __popc(selm));
        atomicAdd(&g_cnt[b], __popc(selm));
    }
    if (lane == 0 && bndm) atomicOr(&g_bnd[b], 1);
    base = __shfl_sync(0xffffffffu, base, 0);
    if (s) g_list[base + __popc(selm & ((1u << lane) - 1u))] = p;
}

// ---------------------------------------------------------------------------
// 3. main: 4 pixels / warp, 8 lanes / pixel (16 channels per lane)
//    24 independent partial dots in registers -> batched 3-stage butterflies
__launch_bounds__(256)
__global__ void ctx_kernel() {
    __shared__ float sacc[BATCH];
    int tid = threadIdx.x;
    int nsel = g_nsel;
    if (blockIdx.x * 32 >= nsel) return;          // uniform per block: all-idle blocks exit
    if (tid < BATCH) sacc[tid] = 0.0f;
    __syncthreads();

    int warp = blockIdx.x * 8 + (tid >> 5);
    int lane = tid & 31;
    int grp  = lane >> 3;                         // pixel group within warp (0..3)
    int sub  = lane & 7;                          // lane within group (0..7)

    int idx = warp * 4 + grp;
    bool active = idx < nsel;
    int p = active ? g_list[idx] : (2 * WW + 2);  // safe interior dummy

    const float4* base = (const float4*)(g_T + (size_t)p * CH);
    float4 c0 = base[sub], c1 = base[sub + 8], c2 = base[sub + 16], c3 = base[sub + 24];
    float invc = g_inv[p];
    unsigned char cp = g_cls[p];

    float dots[24];
#pragma unroll
    for (int j = 0; j < 24; j++) {
        const float4* nb = (const float4*)(g_T + (size_t)(p + c_off[j]) * CH);
        float4 n0 = nb[sub], n1 = nb[sub + 8], n2 = nb[sub + 16], n3 = nb[sub + 24];
        float d;
        d  = c0.x * n0.x + c0.y * n0.y + c0.z * n0.z + c0.w * n0.w;
        d += c1.x * n1.x + c1.y * n1.y + c1.z * n1.z + c1.w * n1.w;
        d += c2.x * n2.x + c2.y * n2.y + c2.z * n2.z + c2.w * n2.w;
        d += c3.x * n3.x + c3.y * n3.y + c3.z * n3.z + c3.w * n3.w;
        dots[j] = d;
    }
    // 24 independent butterflies over the 8-lane group (ILP-friendly)
#pragma unroll
    for (int m = 1; m <= 4; m <<= 1) {
#pragma unroll
        for (int j = 0; j < 24; j++)
            dots[j] += __shfl_xor_sync(0xffffffffu, dots[j], m);
    }

    // epilogue: lane handles neighbors {sub, sub+8, sub+16}
    float acc = 0.0f;
    if (active) {
#pragma unroll
        for (int t = 0; t < 3; t++) {
            int j = sub + 8 * t;
            int q = p + c_off[j];
            float cosv = dots[j] * invc * g_inv[q];
            float lab  = (g_cls[q] == cp) ? 1.0f : 0.0f;
            float e = cosv - lab;
            acc += e * e;
        }
    }
#pragma unroll
    for (int m = 1; m <= 4; m <<= 1)
        acc += __shfl_xor_sync(0xffffffffu, acc, m);
    if (sub == 0 && active) atomicAdd(&sacc[p / HW], acc);

    __syncthreads();
    if (tid < BATCH) {
        float v = sacc[tid];
        if (v != 0.0f) atomicAdd(&g_acc[tid], v);
    }
}

// ---------------------------------------------------------------------------
// 4. finalize
__global__ void fin_kernel(float* __restrict__ out) {
    if (threadIdx.x == 0) {
        float tot = 0.0f, nv = 0.0f;
        for (int b = 0; b < BATCH; b++) {
            float lb = g_acc[b] / fmaxf((float)g_cnt[b], 1.0f) / 24.0f;
            if (g_bnd[b]) { tot += lb; nv += 1.0f; }
        }
        tot = tot / fmaxf(nv, 1.0f);
        if (isnan(tot)) tot = 0.0f;
        out[0] = tot;
    }
}

// ---------------------------------------------------------------------------
extern "C" void kernel_launch(void* const* d_in, const int* in_sizes, int n_in,
                              void* d_out, int out_size) {
    const float* er  = (const float*)d_in[0];
    const int*   seg = (const int*)d_in[1];
    const int*   gtb = (const int*)d_in[2];
    float*       out = (float*)d_out;

    zero_kernel<<<256, 256>>>();
    transpose_kernel<<<dim3(HW / 32, CH / 32, BATCH), dim3(32, 8)>>>(er);
    prep_kernel<<<NPIX / 256, 256>>>(seg, gtb);
    ctx_kernel<<<CTX_BLOCKS, 256>>>();
    fin_kernel<<<1, 32>>>(out);
}

// round 4
// speedup vs baseline: 3.6604x; 1.6572x over previous
#include <cuda_runtime.h>
#include <cuda_fp16.h>
#include <math.h>

#define BATCH 4
#define CH    128
#define HH    384
#define WW    384
#define HW    (HH*WW)          // 147456
#define NPIX  (BATCH*HW)       // 589824

#define MAXSEL ((HH-4)*(WW-4)*BATCH)      // 577600
#define CTX_BLOCKS (((MAXSEL + 3) / 4 + 7) / 8)

// Scratch (allocation-free: __device__ globals)
__device__ __half        g_Th[(size_t)NPIX * CH]; // [B,H,W,C] fp16 features (151 MB)
__device__ float         g_inv[NPIX];             // 1 / max(||f||, 1e-8)  (fp32-exact)
__device__ unsigned char g_cls[NPIX];             // class (seg_label channel 1)
__device__ int           g_list[NPIX];            // compacted selected pixel ids
__device__ int           g_nsel;
__device__ float         g_acc[BATCH];
__device__ int           g_cnt[BATCH];
__device__ int           g_bnd[BATCH];

__constant__ int c_off[24] = {
    -770,-769,-768,-767,-766,
    -386,-385,-384,-383,-382,
      -2,  -1,   1,   2,
     382, 383, 384, 385, 386,
     766, 767, 768, 769, 770 };

// ---------------------------------------------------------------------------
// 0. zero the tiny accumulators only (nf2 pass eliminated)
__global__ void zero_kernel() {
    if (threadIdx.x == 0) g_nsel = 0;
    if (threadIdx.x < BATCH) {
        g_acc[threadIdx.x] = 0.0f;
        g_cnt[threadIdx.x] = 0;
        g_bnd[threadIdx.x] = 0;
    }
}

// ---------------------------------------------------------------------------
// 1. transpose [B,C,H,W] -> [B,H,W,C] fp16, fused exact fp32 norm -> g_inv
//    block owns 32 pixels x ALL 128 channels (4 chunk iterations)
__global__ void transpose_kernel(const float* __restrict__ er) {
    __shared__ float tile[32][33];    // [channel][pixel]
    __shared__ float red[8][32];
    int tx = threadIdx.x, ty = threadIdx.y;
    int t  = ty * 32 + tx;
    int p0 = blockIdx.x * 32;
    int b  = blockIdx.y;
    int px = t >> 3;                  // output pixel 0..31
    int j  = t & 7;                   // output half2-pair index 0..7 (and +8)

    __half2* outp = (__half2*)g_Th + ((size_t)(b * HW) + p0) * (CH / 2);

    float sq = 0.0f;
    for (int c0 = 0; c0 < CH; c0 += 32) {
        if (c0) __syncthreads();
#pragma unroll
        for (int i = 0; i < 4; i++) {
            int c = c0 + ty + 8 * i;
            float v = er[((size_t)(b * CH + c)) * HW + p0 + tx];  // coalesced over tx
            tile[ty + 8 * i][tx] = v;
            sq += v * v;
        }
        __syncthreads();
#pragma unroll
        for (int k = 0; k < 2; k++) {
            int jj = j + 8 * k;                    // 0..15 -> channels 2jj,2jj+1
            __half2 h = __floats2half2_rn(tile[2 * jj][px], tile[2 * jj + 1][px]);
            outp[(size_t)px * (CH / 2) + c0 / 2 + jj] = h;
        }
    }
    red[ty][tx] = sq;
    __syncthreads();
    if (ty == 0) {
        float s = 0.0f;
#pragma unroll
        for (int k = 0; k < 8; k++) s += red[k][tx];
        g_inv[b * HW + p0 + tx] = 1.0f / fmaxf(sqrtf(s), 1e-8f);
    }
}

// ---------------------------------------------------------------------------
// 2. prep: selection mask + compaction, class byte, counts (no norm dep)
__global__ void prep_kernel(const int* __restrict__ seg, const int* __restrict__ gtb) {
    int p = blockIdx.x * blockDim.x + threadIdx.x;   // grid == NPIX exactly
    int b = p / HW;
    int rem = p - b * HW;
    int y = rem / WW;
    int x = rem - y * WW;
    int lane = threadIdx.x & 31;

    int s1r = seg[((size_t)(b * 2 + 1)) * HW + rem];
    int gt = gtb[p];                 if (gt == 255) gt = 0;
    int s1 = s1r;                    if (s1 == 255) s1 = 0;
    bool bnd = (gt * s1) > 0;
    bool inter = (y >= 2) && (y <= HH - 3) && (x >= 2) && (x <= WW - 3);
    bool s = bnd && inter;

    g_cls[p] = (unsigned char)s1r;

    unsigned selm = __ballot_sync(0xffffffffu, s);
    unsigned bndm = __ballot_sync(0xffffffffu, bnd);
    int base = 0;
    if (lane == 0 && selm) {
        base = atomicAdd(&g_nsel, __popc(selm));
        atomicAdd(&g_cnt[b], __popc(selm));
    }
    if (lane == 0 && bndm) atomicOr(&g_bnd[b], 1);
    base = __shfl_sync(0xffffffffu, base, 0);
    if (s) g_list[base + __popc(selm & ((1u << lane) - 1u))] = p;
}

// ---------------------------------------------------------------------------
// 3. main: 4 pixels/warp, 8 lanes/pixel, fp16 features (2x LDG.128 / neighbor)
//    fp32 accumulation; 24 independent 3-stage butterflies
__launch_bounds__(256)
__global__ void ctx_kernel() {
    __shared__ float sacc[BATCH];
    int tid = threadIdx.x;
    int nsel = g_nsel;
    if (blockIdx.x * 32 >= nsel) return;
    if (tid < BATCH) sacc[tid] = 0.0f;
    __syncthreads();

    int warp = blockIdx.x * 8 + (tid >> 5);
    int lane = tid & 31;
    int grp  = lane >> 3;
    int sub  = lane & 7;

    int idx = warp * 4 + grp;
    bool active = idx < nsel;
    int p = active ? g_list[idx] : (2 * WW + 2);

    // center: lane covers channels [8*sub,8*sub+8) and [64+8*sub, ...)
    const float4* base = (const float4*)(g_Th + (size_t)p * CH);
    float4 ca = base[sub], cb = base[sub + 8];
    float cf[16];
    {
        const __half2* h = (const __half2*)&ca;
#pragma unroll
        for (int k = 0; k < 4; k++) { float2 f = __half22float2(h[k]); cf[2*k] = f.x; cf[2*k+1] = f.y; }
        h = (const __half2*)&cb;
#pragma unroll
        for (int k = 0; k < 4; k++) { float2 f = __half22float2(h[k]); cf[8+2*k] = f.x; cf[8+2*k+1] = f.y; }
    }
    float invc = g_inv[p];
    unsigned char cp = g_cls[p];

    float dots[24];
#pragma unroll
    for (int j = 0; j < 24; j++) {
        const float4* nb = (const float4*)(g_Th + (size_t)(p + c_off[j]) * CH);
        float4 na = nb[sub], nbv = nb[sub + 8];
        float d = 0.0f;
        const __half2* h = (const __half2*)&na;
#pragma unroll
        for (int k = 0; k < 4; k++) {
            float2 f = __half22float2(h[k]);
            d += cf[2*k] * f.x + cf[2*k+1] * f.y;
        }
        h = (const __half2*)&nbv;
#pragma unroll
        for (int k = 0; k < 4; k++) {
            float2 f = __half22float2(h[k]);
            d += cf[8+2*k] * f.x + cf[8+2*k+1] * f.y;
        }
        dots[j] = d;
    }
#pragma unroll
    for (int m = 1; m <= 4; m <<= 1) {
#pragma unroll
        for (int j = 0; j < 24; j++)
            dots[j] += __shfl_xor_sync(0xffffffffu, dots[j], m);
    }

    float acc = 0.0f;
    if (active) {
#pragma unroll
        for (int t = 0; t < 3; t++) {
            int j = sub + 8 * t;
            int q = p + c_off[j];
            float cosv = dots[j] * invc * g_inv[q];
            float lab  = (g_cls[q] == cp) ? 1.0f : 0.0f;
            float e = cosv - lab;
            acc += e * e;
        }
    }
#pragma unroll
    for (int m = 1; m <= 4; m <<= 1)
        acc += __shfl_xor_sync(0xffffffffu, acc, m);
    if (sub == 0 && active) atomicAdd(&sacc[p / HW], acc);

    __syncthreads();
    if (tid < BATCH) {
        float v = sacc[tid];
        if (v != 0.0f) atomicAdd(&g_acc[tid], v);
    }
}

// ---------------------------------------------------------------------------
// 4. finalize
__global__ void fin_kernel(float* __restrict__ out) {
    if (threadIdx.x == 0) {
        float tot = 0.0f, nv = 0.0f;
        for (int b = 0; b < BATCH; b++) {
            float lb = g_acc[b] / fmaxf((float)g_cnt[b], 1.0f) / 24.0f;
            if (g_bnd[b]) { tot += lb; nv += 1.0f; }
        }
        tot = tot / fmaxf(nv, 1.0f);
        if (isnan(tot)) tot = 0.0f;
        out[0] = tot;
    }
}

// ---------------------------------------------------------------------------
extern "C" void kernel_launch(void* const* d_in, const int* in_sizes, int n_in,
                              void* d_out, int out_size) {
    const float* er  = (const float*)d_in[0];
    const int*   seg = (const int*)d_in[1];
    const int*   gtb = (const int*)d_in[2];
    float*       out = (float*)d_out;

    zero_kernel<<<1, 32>>>();
    transpose_kernel<<<dim3(HW / 32, BATCH), dim3(32, 8)>>>(er);
    prep_kernel<<<NPIX / 256, 256>>>(seg, gtb);
    ctx_kernel<<<CTX_BLOCKS, 256>>>();
    fin_kernel<<<1, 32>>>(out);
}

// round 5
// speedup vs baseline: 4.1271x; 1.1275x over previous
#include <cuda_runtime.h>
#include <cuda_fp16.h>
#include <math.h>

#define BATCH 4
#define CH    128
#define HH    384
#define WW    384
#define HW    (HH*WW)          // 147456
#define NPIX  (BATCH*HW)       // 589824

#define MAXSEL ((HH-4)*(WW-4)*BATCH)      // 577600
#define CTX_BLOCKS (((MAXSEL + 3) / 4 + 7) / 8)   // 18050

// Scratch (allocation-free: __device__ globals)
__device__ __half        g_Th[(size_t)NPIX * CH]; // [B,H,W,C] fp16 features (151 MB)
__device__ float         g_inv[NPIX];             // 1 / max(||f||, 1e-8)  (fp32-exact)
__device__ unsigned char g_cls[NPIX];             // class (seg_label channel 1)
__device__ int           g_list[NPIX];            // compacted selected pixel ids
__device__ int           g_nsel;
__device__ float         g_acc[BATCH];
__device__ int           g_cnt[BATCH];
__device__ int           g_bnd[BATCH];
__device__ int           g_done;

__constant__ int c_off[24] = {
    -770,-769,-768,-767,-766,
    -386,-385,-384,-383,-382,
      -2,  -1,   1,   2,
     382, 383, 384, 385, 386,
     766, 767, 768, 769, 770 };

// ---------------------------------------------------------------------------
// 0. zero the tiny accumulators
__global__ void zero_kernel() {
    if (threadIdx.x == 0) { g_nsel = 0; g_done = 0; }
    if (threadIdx.x < BATCH) {
        g_acc[threadIdx.x] = 0.0f;
        g_cnt[threadIdx.x] = 0;
        g_bnd[threadIdx.x] = 0;
    }
}

// ---------------------------------------------------------------------------
// 1. transpose [B,C,H,W] -> [B,H,W,C] fp16, fused fp32 inv-norm AND prep
//    (mask + compaction + class byte). Block owns 32 pixels x 128 channels.
__global__ void transpose_kernel(const float* __restrict__ er,
                                 const int* __restrict__ seg,
                                 const int* __restrict__ gtb) {
    __shared__ float tile[32][33];    // [channel][pixel]
    __shared__ float red[8][32];
    int tx = threadIdx.x, ty = threadIdx.y;
    int t  = ty * 32 + tx;
    int p0 = blockIdx.x * 32;
    int b  = blockIdx.y;
    int px = t >> 3;                  // output pixel 0..31
    int j  = t & 7;                   // half2-pair index

    __half2* outp = (__half2*)g_Th + ((size_t)(b * HW) + p0) * (CH / 2);

    float sq = 0.0f;
    for (int c0 = 0; c0 < CH; c0 += 32) {
        if (c0) __syncthreads();
#pragma unroll
        for (int i = 0; i < 4; i++) {
            int c = c0 + ty + 8 * i;
            float v = er[((size_t)(b * CH + c)) * HW + p0 + tx];  // coalesced over tx
            tile[ty + 8 * i][tx] = v;
            sq += v * v;
        }
        __syncthreads();
#pragma unroll
        for (int k = 0; k < 2; k++) {
            int jj = j + 8 * k;
            __half2 h = __floats2half2_rn(tile[2 * jj][px], tile[2 * jj + 1][px]);
            outp[(size_t)px * (CH / 2) + c0 / 2 + jj] = h;
        }
    }
    red[ty][tx] = sq;
    __syncthreads();
    if (ty == 0) {   // warp 0: inv-norm + prep for this block's 32 pixels
        float s = 0.0f;
#pragma unroll
        for (int k = 0; k < 8; k++) s += red[k][tx];
        int rem = p0 + tx;
        int p   = b * HW + rem;
        g_inv[p] = 1.0f / fmaxf(sqrtf(s), 1e-8f);

        int y = rem / WW;
        int x = rem - y * WW;
        int s1r = seg[((size_t)(b * 2 + 1)) * HW + rem];
        int gt  = gtb[p];            if (gt == 255) gt = 0;
        int s1  = s1r;               if (s1 == 255) s1 = 0;
        bool bnd = (gt * s1) > 0;
        bool inter = (y >= 2) && (y <= HH - 3) && (x >= 2) && (x <= WW - 3);
        bool sel = bnd && inter;
        g_cls[p] = (unsigned char)s1r;

        unsigned selm = __ballot_sync(0xffffffffu, sel);
        unsigned bndm = __ballot_sync(0xffffffffu, bnd);
        int base = 0;
        if (tx == 0 && selm) {
            base = atomicAdd(&g_nsel, __popc(selm));
            atomicAdd(&g_cnt[b], __popc(selm));
        }
        if (tx == 0 && bndm) atomicOr(&g_bnd[b], 1);
        base = __shfl_sync(0xffffffffu, base, 0);
        if (sel) g_list[base + __popc(selm & ((1u << tx) - 1u))] = p;
    }
}

// ---------------------------------------------------------------------------
// 2. main: 4 pixels/warp, 8 lanes/pixel; packed HFMA2 dot chains; fused finalize
__launch_bounds__(256)
__global__ void ctx_kernel(float* __restrict__ out) {
    __shared__ float sacc[BATCH];
    int tid  = threadIdx.x;
    int nsel = g_nsel;

    if (blockIdx.x * 32 < nsel) {
        if (tid < BATCH) sacc[tid] = 0.0f;
        __syncthreads();

        int warp = blockIdx.x * 8 + (tid >> 5);
        int lane = tid & 31;
        int grp  = lane >> 3;
        int sub  = lane & 7;

        int idx = warp * 4 + grp;
        bool active = idx < nsel;
        int p = active ? g_list[idx] : (2 * WW + 2);

        // center: 16 channels per lane as 8 half2
        const float4* base4 = (const float4*)(g_Th + (size_t)p * CH);
        float4 ca = base4[sub], cb = base4[sub + 8];
        __half2 ch[8];
        {
            const __half2* h = (const __half2*)&ca;
#pragma unroll
            for (int k = 0; k < 4; k++) ch[k] = h[k];
            h = (const __half2*)&cb;
#pragma unroll
            for (int k = 0; k < 4; k++) ch[4 + k] = h[k];
        }
        float invc = g_inv[p];
        unsigned char cp = g_cls[p];

        float dots[24];
#pragma unroll
        for (int j = 0; j < 24; j++) {
            const float4* nb4 = (const float4*)(g_Th + (size_t)(p + c_off[j]) * CH);
            float4 na = nb4[sub], nb2 = nb4[sub + 8];
            const __half2* ha = (const __half2*)&na;
            const __half2* hb = (const __half2*)&nb2;
            __half2 d = __hmul2(ch[0], ha[0]);
            d = __hfma2(ch[1], ha[1], d);
            d = __hfma2(ch[2], ha[2], d);
            d = __hfma2(ch[3], ha[3], d);
            d = __hfma2(ch[4], hb[0], d);
            d = __hfma2(ch[5], hb[1], d);
            d = __hfma2(ch[6], hb[2], d);
            d = __hfma2(ch[7], hb[3], d);
            float2 f2 = __half22float2(d);
            dots[j] = f2.x + f2.y;
        }
#pragma unroll
        for (int m = 1; m <= 4; m <<= 1) {
#pragma unroll
            for (int j = 0; j < 24; j++)
                dots[j] += __shfl_xor_sync(0xffffffffu, dots[j], m);
        }

        float acc = 0.0f;
        if (active) {
#pragma unroll
            for (int t = 0; t < 3; t++) {
                int j = sub + 8 * t;
                int q = p + c_off[j];
                float cosv = dots[j] * invc * g_inv[q];
                float lab  = (g_cls[q] == cp) ? 1.0f : 0.0f;
                float e = cosv - lab;
                acc += e * e;
            }
        }
#pragma unroll
        for (int m = 1; m <= 4; m <<= 1)
            acc += __shfl_xor_sync(0xffffffffu, acc, m);
        if (sub == 0 && active) atomicAdd(&sacc[p / HW], acc);

        __syncthreads();
        if (tid < BATCH) {
            float v = sacc[tid];
            if (v != 0.0f) atomicAdd(&g_acc[tid], v);
        }
        __syncthreads();
    }

    // fused finalize: last block to retire computes the scalar output
    if (tid == 0) {
        __threadfence();
        int done = atomicAdd(&g_done, 1);
        if (done == (int)gridDim.x - 1) {
            float tot = 0.0f, nv = 0.0f;
            for (int b = 0; b < BATCH; b++) {
                float lb = g_acc[b] / fmaxf((float)g_cnt[b], 1.0f) / 24.0f;
                if (g_bnd[b]) { tot += lb; nv += 1.0f; }
            }
            tot = tot / fmaxf(nv, 1.0f);
            if (isnan(tot)) tot = 0.0f;
            out[0] = tot;
        }
    }
}

// ---------------------------------------------------------------------------
extern "C" void kernel_launch(void* const* d_in, const int* in_sizes, int n_in,
                              void* d_out, int out_size) {
    const float* er  = (const float*)d_in[0];
    const int*   seg = (const int*)d_in[1];
    const int*   gtb = (const int*)d_in[2];
    float*       out = (float*)d_out;

    zero_kernel<<<1, 32>>>();
    transpose_kernel<<<dim3(HW / 32, BATCH), dim3(32, 8)>>>(er, seg, gtb);
    ctx_kernel<<<CTX_BLOCKS, 256>>>(out);
}